// round 14
// baseline (speedup 1.0000x reference)
#include <cuda_runtime.h>
#include <cuda_bf16.h>

#define N_NODES 100000
#define E_EDGES 1600000
#define DIN     256
#define DHID    64
#define DOUT    40
#define PROP_STEPS 16

// Scratch (allocation-free rule: __device__ globals)
__device__ float g_Y0[N_NODES * DHID];
__device__ float g_Y1[N_NODES * DHID];
__device__ float g_src[N_NODES * DHID];
__device__ int   g_row_ptr[N_NODES + 1];

// ---------------------------------------------------------------------------
// Kernel 1: CSR row pointers from sorted edge_row via per-thread lower_bound
// ---------------------------------------------------------------------------
__global__ void build_rowptr_kernel(const int* __restrict__ edge_row) {
    int r = blockIdx.x * blockDim.x + threadIdx.x;
    if (r > N_NODES) return;
    int lo = 0, hi = E_EDGES;
    while (lo < hi) {
        int mid = (lo + hi) >> 1;
        if (edge_row[mid] < r) lo = mid + 1; else hi = mid;
    }
    g_row_ptr[r] = lo;
}

// ---------------------------------------------------------------------------
// bf16 hi/lo split helpers for the tensor-core GEMM
// ---------------------------------------------------------------------------
__device__ __forceinline__ void split2(float a, float b, unsigned& hi, unsigned& lo) {
    __nv_bfloat16 ha = __float2bfloat16_rn(a);
    __nv_bfloat16 hb = __float2bfloat16_rn(b);
    float ra = a - __bfloat162float(ha);
    float rb = b - __bfloat162float(hb);
    __nv_bfloat162 H = __halves2bfloat162(ha, hb);
    __nv_bfloat162 L = __halves2bfloat162(__float2bfloat16_rn(ra),
                                          __float2bfloat16_rn(rb));
    hi = reinterpret_cast<unsigned&>(H);
    lo = reinterpret_cast<unsigned&>(L);
}

__device__ __forceinline__ void mma_bf16(float* c, const unsigned* a,
                                         unsigned b0, unsigned b1) {
    asm volatile(
        "mma.sync.aligned.m16n8k16.row.col.f32.bf16.bf16.f32 "
        "{%0,%1,%2,%3}, {%4,%5,%6,%7}, {%8,%9}, {%0,%1,%2,%3};"
        : "+f"(c[0]), "+f"(c[1]), "+f"(c[2]), "+f"(c[3])
        : "r"(a[0]), "r"(a[1]), "r"(a[2]), "r"(a[3]), "r"(b0), "r"(b1));
}

// ---------------------------------------------------------------------------
// Kernel 2 (tensor): h = x @ W1 + b1 ; Y0 = h ; src = 0.5 * diag * h
// (Exact R8 version — best measured total configuration.)
// ---------------------------------------------------------------------------
__global__ __launch_bounds__(256) void gemm1_tensor_kernel(
    const float* __restrict__ x, const float* __restrict__ W1,
    const float* __restrict__ b1, const float* __restrict__ diag)
{
    __shared__ unsigned sBhi[64][72];
    __shared__ unsigned sBlo[64][72];

    const int tid  = threadIdx.x;
    const int w    = tid >> 5;
    const int lane = tid & 31;
    const int g    = lane >> 2;
    const int tc   = lane & 3;

    const int rowbase = blockIdx.x * 128 + w * 16;
    const int r0 = rowbase + g;
    const int r1 = rowbase + g + 8;
    const int r0c = (r0 < N_NODES) ? r0 : N_NODES - 1;
    const int r1c = (r1 < N_NODES) ? r1 : N_NODES - 1;

    const float* xrow0 = x + (size_t)r0c * DIN;
    const float* xrow1 = x + (size_t)r1c * DIN;

    float c[8][4];
    #pragma unroll
    for (int nt = 0; nt < 8; nt++)
        #pragma unroll
        for (int i = 0; i < 4; i++) c[nt][i] = 0.f;

    for (int chunk = 0; chunk < 2; chunk++) {
        const int k0 = chunk * 128;
        __syncthreads();
        for (int idx = tid; idx < 64 * 64; idx += 256) {
            int pr  = idx >> 6;
            int col = idx & 63;
            float w0 = W1[(k0 + 2 * pr)     * DHID + col];
            float w1 = W1[(k0 + 2 * pr + 1) * DHID + col];
            unsigned hi, lo;
            split2(w0, w1, hi, lo);
            sBhi[pr][col] = hi;
            sBlo[pr][col] = lo;
        }
        __syncthreads();

        #pragma unroll
        for (int j = 0; j < 8; j++) {
            const int kg = k0 + j * 16;
            float2 f00 = *(const float2*)(xrow0 + kg + 2 * tc);
            float2 f10 = *(const float2*)(xrow1 + kg + 2 * tc);
            float2 f01 = *(const float2*)(xrow0 + kg + 2 * tc + 8);
            float2 f11 = *(const float2*)(xrow1 + kg + 2 * tc + 8);
            unsigned ahi[4], alo[4];
            split2(f00.x, f00.y, ahi[0], alo[0]);
            split2(f10.x, f10.y, ahi[1], alo[1]);
            split2(f01.x, f01.y, ahi[2], alo[2]);
            split2(f11.x, f11.y, ahi[3], alo[3]);

            const int j8 = j * 8;
            #pragma unroll
            for (int nt = 0; nt < 8; nt++) {
                const int n0 = nt * 8;
                unsigned bh0 = sBhi[j8 + tc][n0 + g];
                unsigned bh1 = sBhi[j8 + tc + 4][n0 + g];
                unsigned bl0 = sBlo[j8 + tc][n0 + g];
                unsigned bl1 = sBlo[j8 + tc + 4][n0 + g];
                mma_bf16(c[nt], ahi, bh0, bh1);
                mma_bf16(c[nt], ahi, bl0, bl1);
                mma_bf16(c[nt], alo, bh0, bh1);
            }
        }
    }

    const float dv0 = (r0 < N_NODES) ? 0.5f * diag[r0] : 0.f;
    const float dv1 = (r1 < N_NODES) ? 0.5f * diag[r1] : 0.f;
    #pragma unroll
    for (int nt = 0; nt < 8; nt++) {
        const int col = nt * 8 + 2 * tc;
        float bb0 = b1[col], bb1 = b1[col + 1];
        if (r0 < N_NODES) {
            float h0 = c[nt][0] + bb0;
            float h1 = c[nt][1] + bb1;
            g_Y0[r0 * DHID + col]      = h0;
            g_Y0[r0 * DHID + col + 1]  = h1;
            g_src[r0 * DHID + col]     = dv0 * h0;
            g_src[r0 * DHID + col + 1] = dv0 * h1;
        }
        if (r1 < N_NODES) {
            float h2 = c[nt][2] + bb0;
            float h3 = c[nt][3] + bb1;
            g_Y0[r1 * DHID + col]      = h2;
            g_Y0[r1 * DHID + col + 1]  = h3;
            g_src[r1 * DHID + col]     = dv1 * h2;
            g_src[r1 * DHID + col + 1] = dv1 * h3;
        }
    }
}

// ---------------------------------------------------------------------------
// Kernel 3: one propagation step. One warp per row; lane owns 2 columns.
// Software-pipelined: metadata for iteration i+1 is prefetched while
// iteration i's gathers are in flight, removing the serial meta->gather
// latency from the exposed critical path. FMA order per 4-block unchanged.
// ---------------------------------------------------------------------------
__global__ __launch_bounds__(256) void prop_kernel(
    const int* __restrict__ ecol, const float* __restrict__ evalv, int phase)
{
    const float* __restrict__ Yin  = phase ? g_Y1 : g_Y0;
    float*       __restrict__ Yout = phase ? g_Y0 : g_Y1;

    int w = (blockIdx.x * blockDim.x + threadIdx.x) >> 5;
    if (w >= N_NODES) return;
    int lane = threadIdx.x & 31;

    int e   = g_row_ptr[w];
    int end = g_row_ptr[w + 1];

    float ax = 0.f, ay = 0.f;

    int n4 = (end - e) & ~3;          // edges handled by the 4-unrolled loop
    int e4 = e + n4;                  // first tail edge

    if (n4 > 0) {
        // preload metadata for the first 4-block
        int   c0 = ecol[e],  c1 = ecol[e + 1],  c2 = ecol[e + 2],  c3 = ecol[e + 3];
        float v0 = evalv[e], v1 = evalv[e + 1], v2 = evalv[e + 2], v3 = evalv[e + 3];

        for (e += 4; e < e4; e += 4) {
            // gathers for the current block (4 independent L2 trips)
            float2 y0 = *(const float2*)&Yin[c0 * DHID + lane * 2];
            float2 y1 = *(const float2*)&Yin[c1 * DHID + lane * 2];
            float2 y2 = *(const float2*)&Yin[c2 * DHID + lane * 2];
            float2 y3 = *(const float2*)&Yin[c3 * DHID + lane * 2];
            // prefetch next block's metadata while gathers are in flight
            int   nc0 = ecol[e],  nc1 = ecol[e + 1],  nc2 = ecol[e + 2],  nc3 = ecol[e + 3];
            float nv0 = evalv[e], nv1 = evalv[e + 1], nv2 = evalv[e + 2], nv3 = evalv[e + 3];
            // accumulate current block
            ax += v0 * y0.x + v1 * y1.x + v2 * y2.x + v3 * y3.x;
            ay += v0 * y0.y + v1 * y1.y + v2 * y2.y + v3 * y3.y;
            c0 = nc0; c1 = nc1; c2 = nc2; c3 = nc3;
            v0 = nv0; v1 = nv1; v2 = nv2; v3 = nv3;
        }
        // drain the last block
        float2 y0 = *(const float2*)&Yin[c0 * DHID + lane * 2];
        float2 y1 = *(const float2*)&Yin[c1 * DHID + lane * 2];
        float2 y2 = *(const float2*)&Yin[c2 * DHID + lane * 2];
        float2 y3 = *(const float2*)&Yin[c3 * DHID + lane * 2];
        ax += v0 * y0.x + v1 * y1.x + v2 * y2.x + v3 * y3.x;
        ay += v0 * y0.y + v1 * y1.y + v2 * y2.y + v3 * y3.y;
    }
    // scalar tail (0..3 edges)
    for (; e4 < end; e4++) {
        int   c = ecol[e4];
        float v = evalv[e4];
        float2 y = *(const float2*)&Yin[c * DHID + lane * 2];
        ax += v * y.x;
        ay += v * y.y;
    }

    float2 yr = *(const float2*)&Yin[w * DHID + lane * 2];
    float2 s  = *(const float2*)&g_src[w * DHID + lane * 2];
    float2 o;
    o.x = 0.5f * (yr.x + ax) + s.x;
    o.y = 0.5f * (yr.y + ay) + s.y;
    *(float2*)&Yout[w * DHID + lane * 2] = o;
}

// ---------------------------------------------------------------------------
// Kernel 4: out = relu(Y) @ W2 + b2.
// ---------------------------------------------------------------------------
__global__ __launch_bounds__(256) void mlp2_kernel(
    const float* __restrict__ W2, const float* __restrict__ b2,
    float* __restrict__ out)
{
    __shared__ float w2s[64][41];
    __shared__ float ys[64][65];
    __shared__ float b2s[DOUT];

    const int tid = threadIdx.x;
    const int row0 = blockIdx.x * 64;

    for (int idx = tid; idx < DHID * DOUT; idx += 256)
        w2s[idx / DOUT][idx % DOUT] = W2[idx];
    if (tid < DOUT) b2s[tid] = b2[tid];

    #pragma unroll
    for (int i = 0; i < 16; i++) {
        int idx = tid + i * 256;
        int r = idx >> 6, c = idx & 63;
        int gr = row0 + r;
        ys[r][c] = (gr < N_NODES) ? fmaxf(g_Y0[gr * DHID + c], 0.f) : 0.f;
    }
    __syncthreads();

    const int row = tid >> 2;
    const int cg  = tid & 3;
    float acc[10];
    #pragma unroll
    for (int i = 0; i < 10; i++) acc[i] = b2s[cg * 10 + i];

    #pragma unroll 8
    for (int j = 0; j < DHID; j++) {
        float yv = ys[row][j];
        #pragma unroll
        for (int i = 0; i < 10; i++)
            acc[i] += yv * w2s[j][cg * 10 + i];
    }

    int gr = row0 + row;
    if (gr < N_NODES) {
        #pragma unroll
        for (int i = 0; i < 10; i++)
            out[gr * DOUT + cg * 10 + i] = acc[i];
    }
}

// ---------------------------------------------------------------------------
extern "C" void kernel_launch(void* const* d_in, const int* in_sizes, int n_in,
                              void* d_out, int out_size)
{
    const float* x     = (const float*)d_in[0];
    const int*   erow  = (const int*)  d_in[1];
    const int*   ecol  = (const int*)  d_in[2];
    const float* evalv = (const float*)d_in[3];
    const float* diag  = (const float*)d_in[4];
    const float* W1    = (const float*)d_in[5];
    const float* b1    = (const float*)d_in[6];
    const float* W2    = (const float*)d_in[7];
    const float* b2    = (const float*)d_in[8];
    float* out = (float*)d_out;

    build_rowptr_kernel<<<(N_NODES + 1 + 255) / 256, 256>>>(erow);

    int gemm_blocks = (N_NODES + 127) / 128;
    gemm1_tensor_kernel<<<gemm_blocks, 256>>>(x, W1, b1, diag);

    int prop_blocks = (N_NODES * 32 + 255) / 256;   // one warp per row
    for (int s = 0; s < PROP_STEPS; s++) {
        prop_kernel<<<prop_blocks, 256>>>(ecol, evalv, s & 1);
    }

    int mlp_blocks = (N_NODES + 63) / 64;
    mlp2_kernel<<<mlp_blocks, 256>>>(W2, b2, out);
}

// round 15
// speedup vs baseline: 1.5873x; 1.5873x over previous
#include <cuda_runtime.h>
#include <cuda_bf16.h>

#define N_NODES 100000
#define E_EDGES 1600000
#define DIN     256
#define DHID    64
#define DOUT    40
#define PROP_STEPS 16

// Scratch (allocation-free rule: __device__ globals)
__device__ float g_Y0[N_NODES * DHID];
__device__ float g_Y1[N_NODES * DHID];
__device__ float g_src[N_NODES * DHID];
__device__ int   g_row_ptr[N_NODES + 1];

// ---------------------------------------------------------------------------
// Kernel 1: CSR row pointers from sorted edge_row via per-thread lower_bound
// ---------------------------------------------------------------------------
__global__ void build_rowptr_kernel(const int* __restrict__ edge_row) {
    int r = blockIdx.x * blockDim.x + threadIdx.x;
    if (r > N_NODES) return;
    int lo = 0, hi = E_EDGES;
    while (lo < hi) {
        int mid = (lo + hi) >> 1;
        if (edge_row[mid] < r) lo = mid + 1; else hi = mid;
    }
    g_row_ptr[r] = lo;
}

// ---------------------------------------------------------------------------
// bf16 hi/lo split helpers for the tensor-core GEMM
// ---------------------------------------------------------------------------
__device__ __forceinline__ void split2(float a, float b, unsigned& hi, unsigned& lo) {
    __nv_bfloat16 ha = __float2bfloat16_rn(a);
    __nv_bfloat16 hb = __float2bfloat16_rn(b);
    float ra = a - __bfloat162float(ha);
    float rb = b - __bfloat162float(hb);
    __nv_bfloat162 H = __halves2bfloat162(ha, hb);
    __nv_bfloat162 L = __halves2bfloat162(__float2bfloat16_rn(ra),
                                          __float2bfloat16_rn(rb));
    hi = reinterpret_cast<unsigned&>(H);
    lo = reinterpret_cast<unsigned&>(L);
}

__device__ __forceinline__ void mma_bf16(float* c, const unsigned* a,
                                         unsigned b0, unsigned b1) {
    asm volatile(
        "mma.sync.aligned.m16n8k16.row.col.f32.bf16.bf16.f32 "
        "{%0,%1,%2,%3}, {%4,%5,%6,%7}, {%8,%9}, {%0,%1,%2,%3};"
        : "+f"(c[0]), "+f"(c[1]), "+f"(c[2]), "+f"(c[3])
        : "r"(a[0]), "r"(a[1]), "r"(a[2]), "r"(a[3]), "r"(b0), "r"(b1));
}

// ---------------------------------------------------------------------------
// Kernel 2 (tensor): h = x @ W1 + b1 ; Y0 = h ; src = 0.5 * diag * h
// (Exact R8 version — best measured total configuration.)
// ---------------------------------------------------------------------------
__global__ __launch_bounds__(256) void gemm1_tensor_kernel(
    const float* __restrict__ x, const float* __restrict__ W1,
    const float* __restrict__ b1, const float* __restrict__ diag)
{
    __shared__ unsigned sBhi[64][72];
    __shared__ unsigned sBlo[64][72];

    const int tid  = threadIdx.x;
    const int w    = tid >> 5;
    const int lane = tid & 31;
    const int g    = lane >> 2;
    const int tc   = lane & 3;

    const int rowbase = blockIdx.x * 128 + w * 16;
    const int r0 = rowbase + g;
    const int r1 = rowbase + g + 8;
    const int r0c = (r0 < N_NODES) ? r0 : N_NODES - 1;
    const int r1c = (r1 < N_NODES) ? r1 : N_NODES - 1;

    const float* xrow0 = x + (size_t)r0c * DIN;
    const float* xrow1 = x + (size_t)r1c * DIN;

    float c[8][4];
    #pragma unroll
    for (int nt = 0; nt < 8; nt++)
        #pragma unroll
        for (int i = 0; i < 4; i++) c[nt][i] = 0.f;

    for (int chunk = 0; chunk < 2; chunk++) {
        const int k0 = chunk * 128;
        __syncthreads();
        for (int idx = tid; idx < 64 * 64; idx += 256) {
            int pr  = idx >> 6;
            int col = idx & 63;
            float w0 = W1[(k0 + 2 * pr)     * DHID + col];
            float w1 = W1[(k0 + 2 * pr + 1) * DHID + col];
            unsigned hi, lo;
            split2(w0, w1, hi, lo);
            sBhi[pr][col] = hi;
            sBlo[pr][col] = lo;
        }
        __syncthreads();

        #pragma unroll
        for (int j = 0; j < 8; j++) {
            const int kg = k0 + j * 16;
            float2 f00 = *(const float2*)(xrow0 + kg + 2 * tc);
            float2 f10 = *(const float2*)(xrow1 + kg + 2 * tc);
            float2 f01 = *(const float2*)(xrow0 + kg + 2 * tc + 8);
            float2 f11 = *(const float2*)(xrow1 + kg + 2 * tc + 8);
            unsigned ahi[4], alo[4];
            split2(f00.x, f00.y, ahi[0], alo[0]);
            split2(f10.x, f10.y, ahi[1], alo[1]);
            split2(f01.x, f01.y, ahi[2], alo[2]);
            split2(f11.x, f11.y, ahi[3], alo[3]);

            const int j8 = j * 8;
            #pragma unroll
            for (int nt = 0; nt < 8; nt++) {
                const int n0 = nt * 8;
                unsigned bh0 = sBhi[j8 + tc][n0 + g];
                unsigned bh1 = sBhi[j8 + tc + 4][n0 + g];
                unsigned bl0 = sBlo[j8 + tc][n0 + g];
                unsigned bl1 = sBlo[j8 + tc + 4][n0 + g];
                mma_bf16(c[nt], ahi, bh0, bh1);
                mma_bf16(c[nt], ahi, bl0, bl1);
                mma_bf16(c[nt], alo, bh0, bh1);
            }
        }
    }

    const float dv0 = (r0 < N_NODES) ? 0.5f * diag[r0] : 0.f;
    const float dv1 = (r1 < N_NODES) ? 0.5f * diag[r1] : 0.f;
    #pragma unroll
    for (int nt = 0; nt < 8; nt++) {
        const int col = nt * 8 + 2 * tc;
        float bb0 = b1[col], bb1 = b1[col + 1];
        if (r0 < N_NODES) {
            float h0 = c[nt][0] + bb0;
            float h1 = c[nt][1] + bb1;
            g_Y0[r0 * DHID + col]      = h0;
            g_Y0[r0 * DHID + col + 1]  = h1;
            g_src[r0 * DHID + col]     = dv0 * h0;
            g_src[r0 * DHID + col + 1] = dv0 * h1;
        }
        if (r1 < N_NODES) {
            float h2 = c[nt][2] + bb0;
            float h3 = c[nt][3] + bb1;
            g_Y0[r1 * DHID + col]      = h2;
            g_Y0[r1 * DHID + col + 1]  = h3;
            g_src[r1 * DHID + col]     = dv1 * h2;
            g_src[r1 * DHID + col + 1] = dv1 * h3;
        }
    }
}

// ---------------------------------------------------------------------------
// Kernel 3: one propagation step (R2 body — proven best across 8 variants).
// Single change: the independent self-row (yr) and src loads are hoisted
// ABOVE the edge loop, adding 2 loads in flight for the whole loop and
// removing their latency from the kernel tail. FMA order unchanged.
// ---------------------------------------------------------------------------
__global__ __launch_bounds__(256) void prop_kernel(
    const int* __restrict__ ecol, const float* __restrict__ evalv, int phase)
{
    const float* __restrict__ Yin  = phase ? g_Y1 : g_Y0;
    float*       __restrict__ Yout = phase ? g_Y0 : g_Y1;

    int w = (blockIdx.x * blockDim.x + threadIdx.x) >> 5;
    if (w >= N_NODES) return;
    int lane = threadIdx.x & 31;

    int e   = g_row_ptr[w];
    int end = g_row_ptr[w + 1];

    // hoisted independent loads (in flight during the whole edge loop)
    float2 yr = *(const float2*)&Yin[w * DHID + lane * 2];
    float2 s  = *(const float2*)&g_src[w * DHID + lane * 2];

    float ax = 0.f, ay = 0.f;

    for (; e + 4 <= end; e += 4) {
        int   c0 = ecol[e],     c1 = ecol[e + 1], c2 = ecol[e + 2], c3 = ecol[e + 3];
        float v0 = evalv[e],    v1 = evalv[e + 1], v2 = evalv[e + 2], v3 = evalv[e + 3];
        float2 y0 = *(const float2*)&Yin[c0 * DHID + lane * 2];
        float2 y1 = *(const float2*)&Yin[c1 * DHID + lane * 2];
        float2 y2 = *(const float2*)&Yin[c2 * DHID + lane * 2];
        float2 y3 = *(const float2*)&Yin[c3 * DHID + lane * 2];
        ax += v0 * y0.x + v1 * y1.x + v2 * y2.x + v3 * y3.x;
        ay += v0 * y0.y + v1 * y1.y + v2 * y2.y + v3 * y3.y;
    }
    for (; e < end; e++) {
        int   c = ecol[e];
        float v = evalv[e];
        float2 y = *(const float2*)&Yin[c * DHID + lane * 2];
        ax += v * y.x;
        ay += v * y.y;
    }

    float2 o;
    o.x = 0.5f * (yr.x + ax) + s.x;
    o.y = 0.5f * (yr.y + ay) + s.y;
    *(float2*)&Yout[w * DHID + lane * 2] = o;
}

// ---------------------------------------------------------------------------
// Kernel 4: out = relu(Y) @ W2 + b2.
// ---------------------------------------------------------------------------
__global__ __launch_bounds__(256) void mlp2_kernel(
    const float* __restrict__ W2, const float* __restrict__ b2,
    float* __restrict__ out)
{
    __shared__ float w2s[64][41];
    __shared__ float ys[64][65];
    __shared__ float b2s[DOUT];

    const int tid = threadIdx.x;
    const int row0 = blockIdx.x * 64;

    for (int idx = tid; idx < DHID * DOUT; idx += 256)
        w2s[idx / DOUT][idx % DOUT] = W2[idx];
    if (tid < DOUT) b2s[tid] = b2[tid];

    #pragma unroll
    for (int i = 0; i < 16; i++) {
        int idx = tid + i * 256;
        int r = idx >> 6, c = idx & 63;
        int gr = row0 + r;
        ys[r][c] = (gr < N_NODES) ? fmaxf(g_Y0[gr * DHID + c], 0.f) : 0.f;
    }
    __syncthreads();

    const int row = tid >> 2;
    const int cg  = tid & 3;
    float acc[10];
    #pragma unroll
    for (int i = 0; i < 10; i++) acc[i] = b2s[cg * 10 + i];

    #pragma unroll 8
    for (int j = 0; j < DHID; j++) {
        float yv = ys[row][j];
        #pragma unroll
        for (int i = 0; i < 10; i++)
            acc[i] += yv * w2s[j][cg * 10 + i];
    }

    int gr = row0 + row;
    if (gr < N_NODES) {
        #pragma unroll
        for (int i = 0; i < 10; i++)
            out[gr * DOUT + cg * 10 + i] = acc[i];
    }
}

// ---------------------------------------------------------------------------
extern "C" void kernel_launch(void* const* d_in, const int* in_sizes, int n_in,
                              void* d_out, int out_size)
{
    const float* x     = (const float*)d_in[0];
    const int*   erow  = (const int*)  d_in[1];
    const int*   ecol  = (const int*)  d_in[2];
    const float* evalv = (const float*)d_in[3];
    const float* diag  = (const float*)d_in[4];
    const float* W1    = (const float*)d_in[5];
    const float* b1    = (const float*)d_in[6];
    const float* W2    = (const float*)d_in[7];
    const float* b2    = (const float*)d_in[8];
    float* out = (float*)d_out;

    build_rowptr_kernel<<<(N_NODES + 1 + 255) / 256, 256>>>(erow);

    int gemm_blocks = (N_NODES + 127) / 128;
    gemm1_tensor_kernel<<<gemm_blocks, 256>>>(x, W1, b1, diag);

    int prop_blocks = (N_NODES * 32 + 255) / 256;   // one warp per row
    for (int s = 0; s < PROP_STEPS; s++) {
        prop_kernel<<<prop_blocks, 256>>>(ecol, evalv, s & 1);
    }

    int mlp_blocks = (N_NODES + 63) / 64;
    mlp2_kernel<<<mlp_blocks, 256>>>(W2, b2, out);
}